// round 12
// baseline (speedup 1.0000x reference)
#include <cuda_runtime.h>
#include <cuda_bf16.h>
#include <cuda_fp16.h>
#include <cstdint>

// B=2,H=8 -> BH=16 heads; L=S=2048; D=64; fp32 in/out.
#define BH        16
#define Ls        2048
#define Dh        64
#define NT        128
#define NTILES    16
#define BROWS     32
#define NTHREADS  512
#define KSTR      72
#define VSTR      136

#define SDPA_TILEW      (128*KSTR + 64*VSTR)
#define SDPA_SMEM_BYTES ((SDPA_TILEW + 256 + 32) * 4)

#define ATTN_TILEW       (128*KSTR)
#define ATTN_SMEM_BYTES  ((4*ATTN_TILEW + 512 + 16) * 4)   // 149568

// Exponent shift: stored values are exp(s/8 - ESH); cancels in normalization.
#define ESH 8.0f

// Packed interleaved hi/lo (bf16 Q/K rows, fp16 V^T).
__device__ uint32_t g_Q [BH * Ls * 64];
__device__ uint32_t g_K [BH * Ls * 64];
__device__ uint32_t g_VT[BH * Dh * 2048];
// Unnormalized shifted exp scratch (fp16) + row sums.
__device__ __half g_EQh[(long)BH * Ls * Ls];
__device__ __half g_EKh[(long)BH * Ls * Ls];
__device__ float g_rsQ[BH * Ls];
__device__ float g_rsK[BH * Ls];

// ---------------- converts ----------------

__global__ void convert_qk_kernel(const float* __restrict__ Q, const float* __restrict__ K)
{
    const unsigned NPAIR = BH * Ls * 32;
    unsigned i = blockIdx.x * 256 + threadIdx.x;
    const float2* src = (i < NPAIR) ? (const float2*)Q : (const float2*)K;
    uint32_t*     dst = (i < NPAIR) ? g_Q : g_K;
    unsigned p = (i < NPAIR) ? i : i - NPAIR;
    float2 v = src[p];
    __nv_bfloat16 hx = __float2bfloat16(v.x), hy = __float2bfloat16(v.y);
    __nv_bfloat162 hh; hh.x = hx; hh.y = hy;
    __nv_bfloat162 ll = __floats2bfloat162_rn(v.x - __bfloat162float(hx),
                                              v.y - __bfloat162float(hy));
    dst[2u*p]     = *reinterpret_cast<uint32_t*>(&hh);
    dst[2u*p + 1] = *reinterpret_cast<uint32_t*>(&ll);
}

__global__ void convert_v_kernel(const float* __restrict__ V)
{
    __shared__ float st[128][65];
    const int bh = blockIdx.x >> 4;
    const int j0 = (blockIdx.x & 15) * 128;
    const int tid = threadIdx.x;
    const float* vb = V + ((long)bh * Ls + j0) * Dh;
    for (int i = tid; i < 128 * 64; i += 256)
        st[i >> 6][i & 63] = vb[i];
    __syncthreads();
    for (int i = tid; i < 64 * 64; i += 256) {
        int d = i >> 6, jp = i & 63;
        float v0 = st[jp*2][d], v1 = st[jp*2 + 1][d];
        __half h0 = __float2half_rn(v0), h1 = __float2half_rn(v1);
        __half2 hh; hh.x = h0; hh.y = h1;
        __half2 ll; ll.x = __float2half_rn(v0 - __half2float(h0));
                    ll.y = __float2half_rn(v1 - __half2float(h1));
        long w = ((long)(bh * Dh + d) * 1024 + (j0 >> 1) + jp) * 2;
        g_VT[w]     = *reinterpret_cast<uint32_t*>(&hh);
        g_VT[w + 1] = *reinterpret_cast<uint32_t*>(&ll);
    }
}

// ---------------- mma helpers ----------------

__device__ __forceinline__ void mma_bf16(float* c, const uint32_t* a, uint32_t b0, uint32_t b1) {
    asm volatile(
        "mma.sync.aligned.m16n8k16.row.col.f32.bf16.bf16.f32 "
        "{%0,%1,%2,%3},{%4,%5,%6,%7},{%8,%9},{%0,%1,%2,%3};\n"
        : "+f"(c[0]), "+f"(c[1]), "+f"(c[2]), "+f"(c[3])
        : "r"(a[0]), "r"(a[1]), "r"(a[2]), "r"(a[3]), "r"(b0), "r"(b1));
}

__device__ __forceinline__ void mma_f16(float* c, const uint32_t* a, uint32_t b0, uint32_t b1) {
    asm volatile(
        "mma.sync.aligned.m16n8k16.row.col.f32.f16.f16.f32 "
        "{%0,%1,%2,%3},{%4,%5,%6,%7},{%8,%9},{%0,%1,%2,%3};\n"
        : "+f"(c[0]), "+f"(c[1]), "+f"(c[2]), "+f"(c[3])
        : "r"(a[0]), "r"(a[1]), "r"(a[2]), "r"(a[3]), "r"(b0), "r"(b1));
}

__device__ __forceinline__ void load_afrag(const uint32_t* __restrict__ g, long rowbase,
                                           int gid, int tig,
                                           uint32_t hi[4][4], uint32_t lo[4][4])
{
    #pragma unroll
    for (int kt = 0; kt < 4; ++kt) {
        long b0 = (rowbase + gid)     * 64 + (kt*8 + tig) * 2;
        long b1 = (rowbase + 8 + gid) * 64 + (kt*8 + tig) * 2;
        uint2 w0 = *(const uint2*)&g[b0];
        uint2 w1 = *(const uint2*)&g[b1];
        uint2 w2 = *(const uint2*)&g[b0 + 8];
        uint2 w3 = *(const uint2*)&g[b1 + 8];
        hi[kt][0] = w0.x; lo[kt][0] = w0.y;
        hi[kt][1] = w1.x; lo[kt][1] = w1.y;
        hi[kt][2] = w2.x; lo[kt][2] = w2.y;
        hi[kt][3] = w3.x; lo[kt][3] = w3.y;
    }
}

// 16-row x 16-col score tile, e = exp(s/8) (sdpa; no shift).
__device__ __forceinline__ void score_exp(const uint32_t* sm, int jg, int gid, int tig,
                                          const uint32_t hi[4][4], const uint32_t lo[4][4],
                                          float e0[4], float e1[4])
{
    float s0[4] = {0,0,0,0}, s1[4] = {0,0,0,0};
    #pragma unroll
    for (int kt = 0; kt < 4; ++kt) {
        const uint32_t* p0 = &sm[(jg + gid)     * KSTR + (kt*8 + tig) * 2];
        const uint32_t* p1 = &sm[(jg + 8 + gid) * KSTR + (kt*8 + tig) * 2];
        uint2 b00 = *(const uint2*)p0;
        uint2 b01 = *(const uint2*)(p0 + 8);
        uint2 b10 = *(const uint2*)p1;
        uint2 b11 = *(const uint2*)(p1 + 8);
        mma_bf16(s0, hi[kt], b00.x, b01.x);
        mma_bf16(s1, hi[kt], b10.x, b11.x);
        mma_bf16(s0, lo[kt], b00.x, b01.x);
        mma_bf16(s1, lo[kt], b10.x, b11.x);
        mma_bf16(s0, hi[kt], b00.y, b01.y);
        mma_bf16(s1, hi[kt], b10.y, b11.y);
    }
    #pragma unroll
    for (int u = 0; u < 4; ++u) {
        e0[u] = __expf(s0[u] * 0.125f);
        e1[u] = __expf(s1[u] * 0.125f);
    }
}

// 32-row x 16-col score tile, e = exp(s/8 - ESH) (attn; shifted for fp16 storage).
__device__ __forceinline__ void score_exp32(const uint32_t* sm, int jg, int gid, int tig,
                                            const uint32_t hi[2][4][4],
                                            const uint32_t lo[2][4][4],
                                            float e[2][2][4])
{
    float s[2][2][4];
    #pragma unroll
    for (int rg = 0; rg < 2; ++rg)
        #pragma unroll
        for (int ng = 0; ng < 2; ++ng)
            #pragma unroll
            for (int u = 0; u < 4; ++u) s[rg][ng][u] = 0.f;

    #pragma unroll
    for (int kt = 0; kt < 4; ++kt) {
        const uint32_t* p0 = &sm[(jg + gid)     * KSTR + (kt*8 + tig) * 2];
        const uint32_t* p1 = &sm[(jg + 8 + gid) * KSTR + (kt*8 + tig) * 2];
        uint2 b00 = *(const uint2*)p0;
        uint2 b01 = *(const uint2*)(p0 + 8);
        uint2 b10 = *(const uint2*)p1;
        uint2 b11 = *(const uint2*)(p1 + 8);
        mma_bf16(s[0][0], hi[0][kt], b00.x, b01.x);
        mma_bf16(s[0][1], hi[0][kt], b10.x, b11.x);
        mma_bf16(s[1][0], hi[1][kt], b00.x, b01.x);
        mma_bf16(s[1][1], hi[1][kt], b10.x, b11.x);
        mma_bf16(s[0][0], lo[0][kt], b00.x, b01.x);
        mma_bf16(s[0][1], lo[0][kt], b10.x, b11.x);
        mma_bf16(s[1][0], lo[1][kt], b00.x, b01.x);
        mma_bf16(s[1][1], lo[1][kt], b10.x, b11.x);
        mma_bf16(s[0][0], hi[0][kt], b00.y, b01.y);
        mma_bf16(s[0][1], hi[0][kt], b10.y, b11.y);
        mma_bf16(s[1][0], hi[1][kt], b00.y, b01.y);
        mma_bf16(s[1][1], hi[1][kt], b10.y, b11.y);
    }
    #pragma unroll
    for (int rg = 0; rg < 2; ++rg)
        #pragma unroll
        for (int ng = 0; ng < 2; ++ng)
            #pragma unroll
            for (int u = 0; u < 4; ++u)
                e[rg][ng][u] = __expf(fmaf(s[rg][ng][u], 0.125f, -ESH));
}

// ---------------- cp.async helpers ----------------

__device__ __forceinline__ void cpasync16(uint32_t smaddr, const void* gptr) {
    asm volatile("cp.async.cg.shared.global [%0], [%1], 16;\n"
                 :: "r"(smaddr), "l"(gptr));
}
#define CP_COMMIT()  asm volatile("cp.async.commit_group;\n" ::: "memory")
#define CP_WAIT(N)   asm volatile("cp.async.wait_group %0;\n" :: "n"(N) : "memory")

// ---------------- attn pass: shifted exp scores (fp16) + row sums ----------------

__global__ void __launch_bounds__(NTHREADS, 1)
attn_exp_kernel()
{
    extern __shared__ uint32_t smw[];
    uint32_t* bufQ[2] = { smw,                 smw + 2*ATTN_TILEW };
    uint32_t* bufK[2] = { smw + ATTN_TILEW,    smw + 3*ATTN_TILEW };
    float* red = (float*)(smw + 4*ATTN_TILEW);   // [2 mats][8 cg][32 rows]

    const int tid  = threadIdx.x;
    const int lane = tid & 31, warp = tid >> 5;
    const int gid  = lane >> 2, tig = lane & 3;
    const int mat  = warp >> 3;          // 0=Q, 1=K
    const int cg   = warp & 7;
    const int jg   = cg * 16;
    const int bh   = blockIdx.x >> 6;
    const int l0   = (blockIdx.x & 63) * BROWS;
    const long rb  = (long)bh * Ls;

    uint32_t ahi[2][4][4], alo[2][4][4];
    {
        const uint32_t* gA = mat ? g_K : g_Q;
        load_afrag(gA, rb + l0,      gid, tig, ahi[0], alo[0]);
        load_afrag(gA, rb + l0 + 16, gid, tig, ahi[1], alo[1]);
    }

    const float4* gQ4 = (const float4*)(g_Q + rb * 64);
    const float4* gK4 = (const float4*)(g_K + rb * 64);
    uint32_t smQ[2], smK[2];
    smQ[0] = (uint32_t)__cvta_generic_to_shared(bufQ[0]);
    smQ[1] = (uint32_t)__cvta_generic_to_shared(bufQ[1]);
    smK[0] = (uint32_t)__cvta_generic_to_shared(bufK[0]);
    smK[1] = (uint32_t)__cvta_generic_to_shared(bufK[1]);

    #define ISSUE_TILE(ct, s) do { \
        const float4* aq = gQ4 + (ct) * 2048; \
        const float4* ak = gK4 + (ct) * 2048; \
        _Pragma("unroll") \
        for (int u = 0; u < 4; ++u) { \
            int i = tid + u*512; int j = i >> 4, qq = i & 15; \
            uint32_t off = (uint32_t)(j * (KSTR/4) + qq) * 16u; \
            cpasync16(smQ[s] + off, aq + i); \
            cpasync16(smK[s] + off, ak + i); \
        } \
        CP_COMMIT(); \
    } while (0)

    __half* ob = (mat ? g_EKh : g_EQh) + (rb + l0) * (long)Ls;

    float ssum[2][2] = {{0.f,0.f},{0.f,0.f}};

    ISSUE_TILE(0, 0);
    #pragma unroll 1
    for (int ct = 0; ct < NTILES; ++ct) {
        const int s = ct & 1;
        if (ct + 1 < NTILES) { ISSUE_TILE(ct + 1, s ^ 1); CP_WAIT(1); }
        else                 { CP_WAIT(0); }
        __syncthreads();

        const uint32_t* mybuf = mat ? bufK[s] : bufQ[s];
        float e[2][2][4];
        score_exp32(mybuf, jg, gid, tig, ahi, alo, e);

        int c0 = ct * NT + jg + tig * 2;
        #pragma unroll
        for (int rg = 0; rg < 2; ++rg) {
            ssum[rg][0] += e[rg][0][0] + e[rg][0][1] + e[rg][1][0] + e[rg][1][1];
            ssum[rg][1] += e[rg][0][2] + e[rg][0][3] + e[rg][1][2] + e[rg][1][3];
            __half* r0 = ob + (long)(rg*16 + gid)     * Ls + c0;
            __half* r1 = ob + (long)(rg*16 + gid + 8) * Ls + c0;
            *(__half2*)r0       = __floats2half2_rn(e[rg][0][0], e[rg][0][1]);
            *(__half2*)(r0 + 8) = __floats2half2_rn(e[rg][1][0], e[rg][1][1]);
            *(__half2*)r1       = __floats2half2_rn(e[rg][0][2], e[rg][0][3]);
            *(__half2*)(r1 + 8) = __floats2half2_rn(e[rg][1][2], e[rg][1][3]);
        }
        __syncthreads();
    }
    #undef ISSUE_TILE

    #pragma unroll
    for (int rg = 0; rg < 2; ++rg)
        #pragma unroll
        for (int h = 0; h < 2; ++h) {
            ssum[rg][h] += __shfl_xor_sync(~0u, ssum[rg][h], 1);
            ssum[rg][h] += __shfl_xor_sync(~0u, ssum[rg][h], 2);
        }
    if (tig == 0) {
        red[mat*256 + cg*32 + gid]      = ssum[0][0];
        red[mat*256 + cg*32 + 8 + gid]  = ssum[0][1];
        red[mat*256 + cg*32 + 16 + gid] = ssum[1][0];
        red[mat*256 + cg*32 + 24 + gid] = ssum[1][1];
    }
    __syncthreads();
    if (tid < 64) {
        int m = tid >> 5, r = tid & 31;
        float t = 0.f;
        #pragma unroll
        for (int c = 0; c < 8; ++c) t += red[m*256 + c*32 + r];
        (m ? g_rsK : g_rsQ)[bh * Ls + l0 + r] = t;
    }
}

// ---------------- merged kernel: sdpa blocks + normalize blocks ----------------
// Grid 5120: blockIdx%5==0 -> sdpa tile (1024 blocks, tensor-bound);
// else -> normalize 8 rows (4096 blocks, DRAM-bound).
// 4:1 launch interleave x ~25:1 duration ratio => steady-state ~127 SMs on sdpa,
// ~20 on normalize: HBM and tensor pipes run concurrently inside one launch
// (stream-level forks serialize under legacy-stream capture; this does not).

__device__ __forceinline__ void sdpa_block_body(float* __restrict__ outO, int bid,
                                                uint32_t* smw)
{
    uint32_t* bufK   = smw;
    uint32_t* bufV   = smw + 128 * KSTR;
    float*    redsum = (float*)(smw + SDPA_TILEW);
    float*    sinv   = redsum + 256;
    float*    redO   = (float*)smw;

    const int tid  = threadIdx.x;
    const int lane = tid & 31, warp = tid >> 5;
    const int gid  = lane >> 2, tig = lane & 3;
    const int rg   = warp >> 3;
    const int cg   = warp & 7;
    const int jg   = cg * 16;
    const int jp0  = cg * 8;
    const int bh   = bid >> 6;
    const int l0   = (bid & 63) * BROWS;
    const long rb  = (long)bh * Ls;

    uint32_t qhi[4][4], qlo[4][4];
    load_afrag(g_Q, rb + l0 + rg * 16, gid, tig, qhi, qlo);

    float oacc[8][4];
    #pragma unroll
    for (int dg = 0; dg < 8; ++dg)
        #pragma unroll
        for (int u = 0; u < 4; ++u) oacc[dg][u] = 0.f;
    float s0sum = 0.f, s1sum = 0.f;

    float4* smK4 = (float4*)bufK;
    float4* smV4 = (float4*)bufV;
    const float4* gK4 = (const float4*)(g_K + rb * 64);
    const float4* gV4 = (const float4*)(g_VT + (long)bh * Dh * 2048);

    float4 pk[4], pv[4];
    #define PREF_KV(ct) do { \
        const float4* ak = gK4 + (ct) * 2048; \
        const float4* av = gV4 + (ct) * 32; \
        _Pragma("unroll") \
        for (int u = 0; u < 4; ++u) { int i = tid + u*512; pk[u] = ak[i]; \
            int d = i >> 5, q = i & 31; pv[u] = av[(long)d * 512 + q]; } \
    } while (0)
    #define STORE_KV() do { \
        _Pragma("unroll") \
        for (int u = 0; u < 4; ++u) { int i = tid + u*512; int j = i >> 4, q = i & 15; \
            smK4[j * (KSTR/4) + q] = pk[u]; \
            int d = i >> 5, q2 = i & 31; smV4[d * (VSTR/4) + q2] = pv[u]; } \
    } while (0)

    PREF_KV(0);
    #pragma unroll 1
    for (int ct = 0; ct < NTILES; ++ct) {
        __syncthreads();
        STORE_KV();
        __syncthreads();
        if (ct + 1 < NTILES) PREF_KV(ct + 1);

        float e0[4], e1[4];
        score_exp(bufK, jg, gid, tig, qhi, qlo, e0, e1);
        s0sum += e0[0] + e0[1] + e1[0] + e1[1];
        s1sum += e0[2] + e0[3] + e1[2] + e1[3];

        uint32_t pa[4];
        { __half2 h;
          h = __floats2half2_rn(e0[0], e0[1]); pa[0] = *(uint32_t*)&h;
          h = __floats2half2_rn(e0[2], e0[3]); pa[1] = *(uint32_t*)&h;
          h = __floats2half2_rn(e1[0], e1[1]); pa[2] = *(uint32_t*)&h;
          h = __floats2half2_rn(e1[2], e1[3]); pa[3] = *(uint32_t*)&h; }

        #pragma unroll
        for (int dg = 0; dg < 8; ++dg) {
            const uint32_t* pp = &bufV[(dg*8 + gid) * VSTR + (jp0 + tig) * 2];
            uint2 w0 = *(const uint2*)pp;
            uint2 w1 = *(const uint2*)(pp + 8);
            mma_f16(oacc[dg], pa, w0.x, w1.x);
            mma_f16(oacc[dg], pa, w0.y, w1.y);
        }
    }
    #undef PREF_KV
    #undef STORE_KV

    s0sum += __shfl_xor_sync(~0u, s0sum, 1); s0sum += __shfl_xor_sync(~0u, s0sum, 2);
    s1sum += __shfl_xor_sync(~0u, s1sum, 1); s1sum += __shfl_xor_sync(~0u, s1sum, 2);
    __syncthreads();
    if (tig == 0) {
        redsum[warp*16 + gid]     = s0sum;
        redsum[warp*16 + 8 + gid] = s1sum;
    }
    __syncthreads();
    if (tid < BROWS) {
        int rgi = tid >> 4, lr = tid & 15;
        float t = 0.f;
        #pragma unroll
        for (int c = 0; c < 8; ++c) t += redsum[(rgi*8 + c)*16 + lr];
        sinv[tid] = 1.0f / t;
    }
    __syncthreads();
    #pragma unroll
    for (int dg = 0; dg < 8; ++dg) {
        float* r = redO + warp * 1024;
        int d = dg*8 + tig*2;
        r[gid*64 + d]           = oacc[dg][0];
        r[gid*64 + d + 1]       = oacc[dg][1];
        r[(gid+8)*64 + d]       = oacc[dg][2];
        r[(gid+8)*64 + d + 1]   = oacc[dg][3];
    }
    __syncthreads();

    float* ob = outO + (rb + l0) * Dh;
    for (int i = tid; i < BROWS * Dh; i += NTHREADS) {
        int r = i >> 6;
        int rgi = r >> 4, lr = r & 15, d = i & 63;
        float v = 0.f;
        #pragma unroll
        for (int c = 0; c < 8; ++c) v += redO[(rgi*8 + c)*1024 + lr*64 + d];
        ob[i] = v * sinv[r];
    }
}

__device__ __forceinline__ void normalize_block_body(float* __restrict__ outAttn, int nb)
{
    const int tid = threadIdx.x;
    const int sub = tid >> 8;     // 0/1: which of 2 rows this pass
    const int i   = tid & 255;    // uint4 index within row (256 per row)
    const int base = nb * 8;

    #pragma unroll
    for (int r2 = 0; r2 < 4; ++r2) {
        int row = base + r2 * 2 + sub;
        const float invq = 1.0f / g_rsQ[row];
        const float invk = 1.0f / g_rsK[row];
        const uint4* eq = (const uint4*)(g_EQh + (long)row * Ls);
        const uint4* ek = (const uint4*)(g_EKh + (long)row * Ls);
        float4* oa = (float4*)(outAttn + (long)row * Ls);
        uint4 a = eq[i], b = ek[i];
        const __half2* ah  = (const __half2*)&a;
        const __half2* bh2 = (const __half2*)&b;
        float2 f0 = __half22float2(ah[0]), f1 = __half22float2(ah[1]);
        float2 f2 = __half22float2(ah[2]), f3 = __half22float2(ah[3]);
        float2 g0 = __half22float2(bh2[0]), g1 = __half22float2(bh2[1]);
        float2 g2 = __half22float2(bh2[2]), g3 = __half22float2(bh2[3]);
        float4 o0, o1;
        o0.x = f0.x*invq + g0.x*invk;  o0.y = f0.y*invq + g0.y*invk;
        o0.z = f1.x*invq + g1.x*invk;  o0.w = f1.y*invq + g1.y*invk;
        o1.x = f2.x*invq + g2.x*invk;  o1.y = f2.y*invq + g2.y*invk;
        o1.z = f3.x*invq + g3.x*invk;  o1.w = f3.y*invq + g3.y*invk;
        oa[i*2]     = o0;
        oa[i*2 + 1] = o1;
    }
}

__global__ void __launch_bounds__(NTHREADS, 1)
sdpa_norm_kernel(float* __restrict__ outO, float* __restrict__ outAttn)
{
    extern __shared__ uint32_t smw[];
    const int bidx = blockIdx.x;
    const int q5 = bidx / 5;
    if (bidx - q5 * 5 == 0) {
        sdpa_block_body(outO, q5, smw);        // 1024 sdpa blocks
    } else {
        normalize_block_body(outAttn, bidx - q5 - 1);   // 4096 normalize blocks
    }
}

// ---------------- launch ----------------

extern "C" void kernel_launch(void* const* d_in, const int* in_sizes, int n_in,
                              void* d_out, int out_size)
{
    const float* q = (const float*)d_in[0];
    const float* k = (const float*)d_in[1];
    const float* v = (const float*)d_in[2];

    float* outO    = (float*)d_out;             // [2,8,2048,64]
    float* outAttn = (float*)d_out + 2097152;   // [2,8,2048,2048]

    cudaFuncSetAttribute(attn_exp_kernel,
                         cudaFuncAttributeMaxDynamicSharedMemorySize, ATTN_SMEM_BYTES);
    cudaFuncSetAttribute(sdpa_norm_kernel,
                         cudaFuncAttributeMaxDynamicSharedMemorySize, SDPA_SMEM_BYTES);

    convert_qk_kernel<<<(2 * BH * Ls * 32) / 256, 256>>>(q, k);
    convert_v_kernel<<<BH * 16, 256>>>(v);
    attn_exp_kernel<<<1024, NTHREADS, ATTN_SMEM_BYTES>>>();
    sdpa_norm_kernel<<<5120, NTHREADS, SDPA_SMEM_BYTES>>>(outO, outAttn);
}

// round 14
// speedup vs baseline: 1.2304x; 1.2304x over previous
#include <cuda_runtime.h>
#include <cuda_bf16.h>
#include <cuda_fp16.h>
#include <cstdint>

// B=2,H=8 -> BH=16 heads; L=S=2048; D=64; fp32 in/out.
#define BH        16
#define Ls        2048
#define Dh        64
#define NT        128
#define NTILES    16
#define BROWS     32
#define NTHREADS  512
#define KSTR      72        // smem words per staged K/Q row (64 data + 8 pad)
#define VSTR2     68        // smem words per staged VT row (64 data + 4 pad)

// sdpa smem: tile region 13568 words, but the epilogue's redO (16 warps x 1024)
// aliases from word 0 and needs 16384 words; redsum/sinv live AFTER that.
#define SDPA_TILEW      (128*KSTR + 64*VSTR2)             // 13568 words
#define SDPA_REDO_W     16384
#define SDPA_SMEM_BYTES ((SDPA_REDO_W + 256 + 32) * 4)    // 66688

#define ATTN_TILEW       (128*KSTR)                        // 9216 words
#define ATTN_SMEM_BYTES  ((2*ATTN_TILEW + 512 + 16) * 4)   // 75840

// Exponent shift: stored values are exp(s/8 - ESH); cancels in normalization.
#define ESH 8.0f

// Packed interleaved hi/lo bf16 Q/K rows; single-fp16 V^T.
__device__ uint32_t g_Q  [BH * Ls * 64];
__device__ uint32_t g_K  [BH * Ls * 64];
__device__ uint32_t g_VTh[BH * Dh * 1024];   // fp16x2 per jpair
// Unnormalized shifted exp scratch (fp16) + row sums.
__device__ __half g_EQh[(long)BH * Ls * Ls];
__device__ __half g_EKh[(long)BH * Ls * Ls];
__device__ float g_rsQ[BH * Ls];
__device__ float g_rsK[BH * Ls];

// ---------------- converts ----------------

__global__ void convert_qk_kernel(const float* __restrict__ Q, const float* __restrict__ K)
{
    const unsigned NPAIR = BH * Ls * 32;
    unsigned i = blockIdx.x * 256 + threadIdx.x;
    const float2* src = (i < NPAIR) ? (const float2*)Q : (const float2*)K;
    uint32_t*     dst = (i < NPAIR) ? g_Q : g_K;
    unsigned p = (i < NPAIR) ? i : i - NPAIR;
    float2 v = src[p];
    __nv_bfloat16 hx = __float2bfloat16(v.x), hy = __float2bfloat16(v.y);
    __nv_bfloat162 hh; hh.x = hx; hh.y = hy;
    __nv_bfloat162 ll = __floats2bfloat162_rn(v.x - __bfloat162float(hx),
                                              v.y - __bfloat162float(hy));
    dst[2u*p]     = *reinterpret_cast<uint32_t*>(&hh);
    dst[2u*p + 1] = *reinterpret_cast<uint32_t*>(&ll);
}

__global__ void convert_v_kernel(const float* __restrict__ V)
{
    __shared__ float st[128][65];
    const int bh = blockIdx.x >> 4;
    const int j0 = (blockIdx.x & 15) * 128;
    const int tid = threadIdx.x;
    const float* vb = V + ((long)bh * Ls + j0) * Dh;
    for (int i = tid; i < 128 * 64; i += 256)
        st[i >> 6][i & 63] = vb[i];
    __syncthreads();
    for (int i = tid; i < 64 * 64; i += 256) {
        int d = i >> 6, jp = i & 63;
        __half2 hh = __floats2half2_rn(st[jp*2][d], st[jp*2 + 1][d]);
        g_VTh[(long)(bh * Dh + d) * 1024 + (j0 >> 1) + jp] =
            *reinterpret_cast<uint32_t*>(&hh);
    }
}

// ---------------- mma helpers ----------------

__device__ __forceinline__ void mma_bf16(float* c, const uint32_t* a, uint32_t b0, uint32_t b1) {
    asm volatile(
        "mma.sync.aligned.m16n8k16.row.col.f32.bf16.bf16.f32 "
        "{%0,%1,%2,%3},{%4,%5,%6,%7},{%8,%9},{%0,%1,%2,%3};\n"
        : "+f"(c[0]), "+f"(c[1]), "+f"(c[2]), "+f"(c[3])
        : "r"(a[0]), "r"(a[1]), "r"(a[2]), "r"(a[3]), "r"(b0), "r"(b1));
}

__device__ __forceinline__ void mma_f16(float* c, const uint32_t* a, uint32_t b0, uint32_t b1) {
    asm volatile(
        "mma.sync.aligned.m16n8k16.row.col.f32.f16.f16.f32 "
        "{%0,%1,%2,%3},{%4,%5,%6,%7},{%8,%9},{%0,%1,%2,%3};\n"
        : "+f"(c[0]), "+f"(c[1]), "+f"(c[2]), "+f"(c[3])
        : "r"(a[0]), "r"(a[1]), "r"(a[2]), "r"(a[3]), "r"(b0), "r"(b1));
}

__device__ __forceinline__ void load_afrag(const uint32_t* __restrict__ g, long rowbase,
                                           int gid, int tig,
                                           uint32_t hi[4][4], uint32_t lo[4][4])
{
    #pragma unroll
    for (int kt = 0; kt < 4; ++kt) {
        long b0 = (rowbase + gid)     * 64 + (kt*8 + tig) * 2;
        long b1 = (rowbase + 8 + gid) * 64 + (kt*8 + tig) * 2;
        uint2 w0 = *(const uint2*)&g[b0];
        uint2 w1 = *(const uint2*)&g[b1];
        uint2 w2 = *(const uint2*)&g[b0 + 8];
        uint2 w3 = *(const uint2*)&g[b1 + 8];
        hi[kt][0] = w0.x; lo[kt][0] = w0.y;
        hi[kt][1] = w1.x; lo[kt][1] = w1.y;
        hi[kt][2] = w2.x; lo[kt][2] = w2.y;
        hi[kt][3] = w3.x; lo[kt][3] = w3.y;
    }
}

// 16-row x 16-col score tile, e = exp(s/8) (sdpa; no shift).
__device__ __forceinline__ void score_exp(const uint32_t* sm, int jg, int gid, int tig,
                                          const uint32_t hi[4][4], const uint32_t lo[4][4],
                                          float e0[4], float e1[4])
{
    float s0[4] = {0,0,0,0}, s1[4] = {0,0,0,0};
    #pragma unroll
    for (int kt = 0; kt < 4; ++kt) {
        const uint32_t* p0 = &sm[(jg + gid)     * KSTR + (kt*8 + tig) * 2];
        const uint32_t* p1 = &sm[(jg + 8 + gid) * KSTR + (kt*8 + tig) * 2];
        uint2 b00 = *(const uint2*)p0;
        uint2 b01 = *(const uint2*)(p0 + 8);
        uint2 b10 = *(const uint2*)p1;
        uint2 b11 = *(const uint2*)(p1 + 8);
        mma_bf16(s0, hi[kt], b00.x, b01.x);
        mma_bf16(s1, hi[kt], b10.x, b11.x);
        mma_bf16(s0, lo[kt], b00.x, b01.x);
        mma_bf16(s1, lo[kt], b10.x, b11.x);
        mma_bf16(s0, hi[kt], b00.y, b01.y);
        mma_bf16(s1, hi[kt], b10.y, b11.y);
    }
    #pragma unroll
    for (int u = 0; u < 4; ++u) {
        e0[u] = __expf(s0[u] * 0.125f);
        e1[u] = __expf(s1[u] * 0.125f);
    }
}

// 32-row x 16-col score tile, e = exp(s/8 - ESH) (attn; shifted for fp16 storage).
__device__ __forceinline__ void score_exp32(const uint32_t* sm, int jg, int gid, int tig,
                                            const uint32_t hi[2][4][4],
                                            const uint32_t lo[2][4][4],
                                            float e[2][2][4])
{
    float s[2][2][4];
    #pragma unroll
    for (int rg = 0; rg < 2; ++rg)
        #pragma unroll
        for (int ng = 0; ng < 2; ++ng)
            #pragma unroll
            for (int u = 0; u < 4; ++u) s[rg][ng][u] = 0.f;

    #pragma unroll
    for (int kt = 0; kt < 4; ++kt) {
        const uint32_t* p0 = &sm[(jg + gid)     * KSTR + (kt*8 + tig) * 2];
        const uint32_t* p1 = &sm[(jg + 8 + gid) * KSTR + (kt*8 + tig) * 2];
        uint2 b00 = *(const uint2*)p0;
        uint2 b01 = *(const uint2*)(p0 + 8);
        uint2 b10 = *(const uint2*)p1;
        uint2 b11 = *(const uint2*)(p1 + 8);
        mma_bf16(s[0][0], hi[0][kt], b00.x, b01.x);
        mma_bf16(s[0][1], hi[0][kt], b10.x, b11.x);
        mma_bf16(s[1][0], hi[1][kt], b00.x, b01.x);
        mma_bf16(s[1][1], hi[1][kt], b10.x, b11.x);
        mma_bf16(s[0][0], lo[0][kt], b00.x, b01.x);
        mma_bf16(s[0][1], lo[0][kt], b10.x, b11.x);
        mma_bf16(s[1][0], lo[1][kt], b00.x, b01.x);
        mma_bf16(s[1][1], lo[1][kt], b10.x, b11.x);
        mma_bf16(s[0][0], hi[0][kt], b00.y, b01.y);
        mma_bf16(s[0][1], hi[0][kt], b10.y, b11.y);
        mma_bf16(s[1][0], hi[1][kt], b00.y, b01.y);
        mma_bf16(s[1][1], hi[1][kt], b10.y, b11.y);
    }
    #pragma unroll
    for (int rg = 0; rg < 2; ++rg)
        #pragma unroll
        for (int ng = 0; ng < 2; ++ng)
            #pragma unroll
            for (int u = 0; u < 4; ++u)
                e[rg][ng][u] = __expf(fmaf(s[rg][ng][u], 0.125f, -ESH));
}

// ---------------- cp.async helpers ----------------

__device__ __forceinline__ void cpasync16(uint32_t smaddr, const void* gptr) {
    asm volatile("cp.async.cg.shared.global [%0], [%1], 16;\n"
                 :: "r"(smaddr), "l"(gptr));
}
#define CP_COMMIT()  asm volatile("cp.async.commit_group;\n" ::: "memory")
#define CP_WAIT(N)   asm volatile("cp.async.wait_group %0;\n" :: "n"(N) : "memory")

// ---------------- attn pass: one matrix per block, 64 rows ----------------
// mat = blockIdx&1 (0=Q, 1=K). Each block stages only its own matrix tiles;
// each staged tile feeds 64 rows of MMAs. 16 warps = 2 rowgroups x 8 colgroups.

__global__ void __launch_bounds__(NTHREADS, 1)
attn_exp_kernel()
{
    extern __shared__ uint32_t smw[];
    uint32_t* buf[2] = { smw, smw + ATTN_TILEW };
    float* red = (float*)(smw + 2*ATTN_TILEW);   // [8 cg][64 rows]

    const int tid  = threadIdx.x;
    const int lane = tid & 31, warp = tid >> 5;
    const int gid  = lane >> 2, tig = lane & 3;
    const int rw   = warp >> 3;          // rowgroup 0/1 -> rows rw*32..+32
    const int cg   = warp & 7;
    const int jg   = cg * 16;
    const int mat  = blockIdx.x & 1;
    const int strip= (blockIdx.x >> 1) & 31;
    const int bh   = blockIdx.x >> 6;
    const int l0   = strip * 64;
    const long rb  = (long)bh * Ls;

    const uint32_t* gA = mat ? g_K : g_Q;

    uint32_t ahi[2][4][4], alo[2][4][4];
    load_afrag(gA, rb + l0 + rw*32,      gid, tig, ahi[0], alo[0]);
    load_afrag(gA, rb + l0 + rw*32 + 16, gid, tig, ahi[1], alo[1]);

    const float4* gA4 = (const float4*)(gA + rb * 64);
    uint32_t smb[2];
    smb[0] = (uint32_t)__cvta_generic_to_shared(buf[0]);
    smb[1] = (uint32_t)__cvta_generic_to_shared(buf[1]);

    #define ISSUE_TILE(ct, s) do { \
        const float4* ap = gA4 + (ct) * 2048; \
        _Pragma("unroll") \
        for (int u = 0; u < 4; ++u) { \
            int i = tid + u*512; int j = i >> 4, qq = i & 15; \
            cpasync16(smb[s] + (uint32_t)(j * (KSTR/4) + qq) * 16u, ap + i); \
        } \
        CP_COMMIT(); \
    } while (0)

    __half* ob = (mat ? g_EKh : g_EQh) + (rb + l0 + rw*32) * (long)Ls;

    float ssum[2][2] = {{0.f,0.f},{0.f,0.f}};

    ISSUE_TILE(0, 0);
    #pragma unroll 1
    for (int ct = 0; ct < NTILES; ++ct) {
        const int s = ct & 1;
        if (ct + 1 < NTILES) { ISSUE_TILE(ct + 1, s ^ 1); CP_WAIT(1); }
        else                 { CP_WAIT(0); }
        __syncthreads();

        float e[2][2][4];
        score_exp32(buf[s], jg, gid, tig, ahi, alo, e);

        int c0 = ct * NT + jg + tig * 2;
        #pragma unroll
        for (int rg = 0; rg < 2; ++rg) {
            ssum[rg][0] += e[rg][0][0] + e[rg][0][1] + e[rg][1][0] + e[rg][1][1];
            ssum[rg][1] += e[rg][0][2] + e[rg][0][3] + e[rg][1][2] + e[rg][1][3];
            __half* r0 = ob + (long)(rg*16 + gid)     * Ls + c0;
            __half* r1 = ob + (long)(rg*16 + gid + 8) * Ls + c0;
            *(__half2*)r0       = __floats2half2_rn(e[rg][0][0], e[rg][0][1]);
            *(__half2*)(r0 + 8) = __floats2half2_rn(e[rg][1][0], e[rg][1][1]);
            *(__half2*)r1       = __floats2half2_rn(e[rg][0][2], e[rg][0][3]);
            *(__half2*)(r1 + 8) = __floats2half2_rn(e[rg][1][2], e[rg][1][3]);
        }
        __syncthreads();
    }
    #undef ISSUE_TILE

    #pragma unroll
    for (int rg = 0; rg < 2; ++rg)
        #pragma unroll
        for (int h = 0; h < 2; ++h) {
            ssum[rg][h] += __shfl_xor_sync(~0u, ssum[rg][h], 1);
            ssum[rg][h] += __shfl_xor_sync(~0u, ssum[rg][h], 2);
        }
    if (tig == 0) {
        red[cg*64 + rw*32 + gid]      = ssum[0][0];
        red[cg*64 + rw*32 + 8 + gid]  = ssum[0][1];
        red[cg*64 + rw*32 + 16 + gid] = ssum[1][0];
        red[cg*64 + rw*32 + 24 + gid] = ssum[1][1];
    }
    __syncthreads();
    if (tid < 64) {
        float t = 0.f;
        #pragma unroll
        for (int c = 0; c < 8; ++c) t += red[c*64 + tid];
        (mat ? g_rsK : g_rsQ)[bh * Ls + l0 + tid] = t;
    }
}

// ---------------- normalize + add: out = EQ/sq + EK/sk ----------------

__global__ void __launch_bounds__(128)
normalize_add_kernel(float* __restrict__ outAttn)
{
    const int row = blockIdx.x;
    const float invq = 1.0f / g_rsQ[row];
    const float invk = 1.0f / g_rsK[row];
    const uint4* eq = (const uint4*)(g_EQh + (long)row * Ls);
    const uint4* ek = (const uint4*)(g_EKh + (long)row * Ls);
    float4* oa = (float4*)(outAttn + (long)row * Ls);
    #pragma unroll
    for (int u = 0; u < 2; ++u) {
        int i = threadIdx.x + u * 128;
        uint4 a = eq[i], b = ek[i];
        const __half2* ah  = (const __half2*)&a;
        const __half2* bh2 = (const __half2*)&b;
        float2 f0 = __half22float2(ah[0]), f1 = __half22float2(ah[1]);
        float2 f2 = __half22float2(ah[2]), f3 = __half22float2(ah[3]);
        float2 g0 = __half22float2(bh2[0]), g1 = __half22float2(bh2[1]);
        float2 g2 = __half22float2(bh2[2]), g3 = __half22float2(bh2[3]);
        float4 o0, o1;
        o0.x = f0.x*invq + g0.x*invk;  o0.y = f0.y*invq + g0.y*invk;
        o0.z = f1.x*invq + g1.x*invk;  o0.w = f1.y*invq + g1.y*invk;
        o1.x = f2.x*invq + g2.x*invk;  o1.y = f2.y*invq + g2.y*invk;
        o1.z = f3.x*invq + g3.x*invk;  o1.w = f3.y*invq + g3.y*invk;
        oa[i*2]     = o0;
        oa[i*2 + 1] = o1;
    }
}

// ---------------- flash-style sdpa: single-fp16 V ----------------

__global__ void __launch_bounds__(NTHREADS, 1)
sdpa_flash_kernel(float* __restrict__ outO)
{
    extern __shared__ uint32_t smw[];
    uint32_t* bufK   = smw;
    uint32_t* bufV   = smw + 128 * KSTR;
    float*    redsum = (float*)(smw + SDPA_REDO_W);   // AFTER redO region
    float*    sinv   = redsum + 256;
    float*    redO   = (float*)smw;   // 16384 floats, aliases tile bufs after loop

    const int tid  = threadIdx.x;
    const int lane = tid & 31, warp = tid >> 5;
    const int gid  = lane >> 2, tig = lane & 3;
    const int rg   = warp >> 3;
    const int cg   = warp & 7;
    const int jg   = cg * 16;
    const int jp0  = cg * 8;
    const int bh   = blockIdx.x >> 6;
    const int l0   = (blockIdx.x & 63) * BROWS;
    const long rb  = (long)bh * Ls;

    uint32_t qhi[4][4], qlo[4][4];
    load_afrag(g_Q, rb + l0 + rg * 16, gid, tig, qhi, qlo);

    float oacc[8][4];
    #pragma unroll
    for (int dg = 0; dg < 8; ++dg)
        #pragma unroll
        for (int u = 0; u < 4; ++u) oacc[dg][u] = 0.f;
    float s0sum = 0.f, s1sum = 0.f;

    float4* smK4 = (float4*)bufK;
    float4* smV4 = (float4*)bufV;
    const float4* gK4 = (const float4*)(g_K + rb * 64);
    const float4* gV4 = (const float4*)(g_VTh + (long)bh * Dh * 1024);

    float4 pk[4], pv[2];
    #define PREF_KV(ct) do { \
        const float4* ak = gK4 + (ct) * 2048; \
        const float4* av = gV4 + (ct) * 16; \
        _Pragma("unroll") \
        for (int u = 0; u < 4; ++u) pk[u] = ak[tid + u*512]; \
        _Pragma("unroll") \
        for (int u = 0; u < 2; ++u) { int i = tid + u*512; \
            pv[u] = av[(long)(i >> 4) * 256 + (i & 15)]; } \
    } while (0)
    #define STORE_KV() do { \
        _Pragma("unroll") \
        for (int u = 0; u < 4; ++u) { int i = tid + u*512; \
            smK4[(i >> 4) * (KSTR/4) + (i & 15)] = pk[u]; } \
        _Pragma("unroll") \
        for (int u = 0; u < 2; ++u) { int i = tid + u*512; \
            smV4[(i >> 4) * (VSTR2/4) + (i & 15)] = pv[u]; } \
    } while (0)

    PREF_KV(0);
    #pragma unroll 1
    for (int ct = 0; ct < NTILES; ++ct) {
        __syncthreads();
        STORE_KV();
        __syncthreads();
        if (ct + 1 < NTILES) PREF_KV(ct + 1);

        float e0[4], e1[4];
        score_exp(bufK, jg, gid, tig, qhi, qlo, e0, e1);
        s0sum += e0[0] + e0[1] + e1[0] + e1[1];
        s1sum += e0[2] + e0[3] + e1[2] + e1[3];

        uint32_t pa[4];
        { __half2 h;
          h = __floats2half2_rn(e0[0], e0[1]); pa[0] = *(uint32_t*)&h;
          h = __floats2half2_rn(e0[2], e0[3]); pa[1] = *(uint32_t*)&h;
          h = __floats2half2_rn(e1[0], e1[1]); pa[2] = *(uint32_t*)&h;
          h = __floats2half2_rn(e1[2], e1[3]); pa[3] = *(uint32_t*)&h; }

        #pragma unroll
        for (int dg = 0; dg < 8; ++dg) {
            uint32_t b0 = bufV[(dg*8 + gid) * VSTR2 + jp0 + tig];
            uint32_t b1 = bufV[(dg*8 + gid) * VSTR2 + jp0 + tig + 4];
            mma_f16(oacc[dg], pa, b0, b1);
        }
    }
    #undef PREF_KV
    #undef STORE_KV

    s0sum += __shfl_xor_sync(~0u, s0sum, 1); s0sum += __shfl_xor_sync(~0u, s0sum, 2);
    s1sum += __shfl_xor_sync(~0u, s1sum, 1); s1sum += __shfl_xor_sync(~0u, s1sum, 2);
    __syncthreads();
    if (tig == 0) {
        redsum[warp*16 + gid]     = s0sum;
        redsum[warp*16 + 8 + gid] = s1sum;
    }
    __syncthreads();
    if (tid < BROWS) {
        int rgi = tid >> 4, lr = tid & 15;
        float t = 0.f;
        #pragma unroll
        for (int c = 0; c < 8; ++c) t += redsum[(rgi*8 + c)*16 + lr];
        sinv[tid] = 1.0f / t;
    }
    __syncthreads();
    #pragma unroll
    for (int dg = 0; dg < 8; ++dg) {
        float* r = redO + warp * 1024;
        int d = dg*8 + tig*2;
        r[gid*64 + d]           = oacc[dg][0];
        r[gid*64 + d + 1]       = oacc[dg][1];
        r[(gid+8)*64 + d]       = oacc[dg][2];
        r[(gid+8)*64 + d + 1]   = oacc[dg][3];
    }
    __syncthreads();

    float* ob = outO + (rb + l0) * Dh;
    for (int i = tid; i < BROWS * Dh; i += NTHREADS) {
        int r = i >> 6;
        int rgi = r >> 4, lr = r & 15, d = i & 63;
        float v = 0.f;
        #pragma unroll
        for (int c = 0; c < 8; ++c) v += redO[(rgi*8 + c)*1024 + lr*64 + d];
        ob[i] = v * sinv[r];
    }
}

// ---------------- launch ----------------

extern "C" void kernel_launch(void* const* d_in, const int* in_sizes, int n_in,
                              void* d_out, int out_size)
{
    const float* q = (const float*)d_in[0];
    const float* k = (const float*)d_in[1];
    const float* v = (const float*)d_in[2];

    float* outO    = (float*)d_out;             // [2,8,2048,64]
    float* outAttn = (float*)d_out + 2097152;   // [2,8,2048,2048]

    cudaFuncSetAttribute(attn_exp_kernel,
                         cudaFuncAttributeMaxDynamicSharedMemorySize, ATTN_SMEM_BYTES);
    cudaFuncSetAttribute(sdpa_flash_kernel,
                         cudaFuncAttributeMaxDynamicSharedMemorySize, SDPA_SMEM_BYTES);

    convert_qk_kernel<<<(2 * BH * Ls * 32) / 256, 256>>>(q, k);
    convert_v_kernel<<<BH * 16, 256>>>(v);
    attn_exp_kernel<<<1024, NTHREADS, ATTN_SMEM_BYTES>>>();
    normalize_add_kernel<<<BH * Ls, 128>>>(outAttn);
    sdpa_flash_kernel<<<1024, NTHREADS, SDPA_SMEM_BYTES>>>(outO);
}

// round 15
// speedup vs baseline: 1.3438x; 1.0921x over previous
#include <cuda_runtime.h>
#include <cuda_bf16.h>
#include <cuda_fp16.h>
#include <cstdint>

// B=2,H=8 -> BH=16 heads; L=S=2048; D=64; fp32 in/out.
#define BH        16
#define Ls        2048
#define Dh        64
#define NT        128
#define NTILES    16
#define NTHREADS  512
#define KSTR      72        // smem words per staged K/Q row (64 data + 8 pad)
#define VSTR3     36        // smem words per staged VT row (32 data + 4 pad)

// sdpa (split-j, 64 rows x 1024 cols per block): tiles 64*72 + 64*36 = 6912 words;
// epilogue redO needs 16 warps x 1024 = 16384 words (aliases from word 0).
#define SDPA_REDO_W     16384
#define SDPA_SMEM_BYTES ((SDPA_REDO_W + 256 + 16) * 4)    // 66624

#define ATTN_TILEW       (128*KSTR)                        // 9216 words
#define ATTN_SMEM_BYTES  ((2*ATTN_TILEW + 512 + 16) * 4)   // 75840

// Exponent shift: stored values are exp(s/8 - ESH); cancels in normalization.
#define ESH 8.0f

// Packed interleaved hi/lo bf16 Q/K rows; single-fp16 V^T.
__device__ uint32_t g_Q  [BH * Ls * 64];
__device__ uint32_t g_K  [BH * Ls * 64];
__device__ uint32_t g_VTh[BH * Dh * 1024];   // fp16x2 per jpair
// Unnormalized shifted exp scratch (fp16) + row sums.
__device__ __half g_EQh[(long)BH * Ls * Ls];
__device__ __half g_EKh[(long)BH * Ls * Ls];
__device__ float g_rsQ[BH * Ls];
__device__ float g_rsK[BH * Ls];
// sdpa split-j partials: [half][row][d] and [half][row].
__device__ float g_Opart[2 * BH * Ls * Dh];
__device__ float g_ssum [2 * BH * Ls];

// ---------------- converts ----------------

__global__ void convert_qk_kernel(const float* __restrict__ Q, const float* __restrict__ K)
{
    const unsigned NPAIR = BH * Ls * 32;
    unsigned i = blockIdx.x * 256 + threadIdx.x;
    const float2* src = (i < NPAIR) ? (const float2*)Q : (const float2*)K;
    uint32_t*     dst = (i < NPAIR) ? g_Q : g_K;
    unsigned p = (i < NPAIR) ? i : i - NPAIR;
    float2 v = src[p];
    __nv_bfloat16 hx = __float2bfloat16(v.x), hy = __float2bfloat16(v.y);
    __nv_bfloat162 hh; hh.x = hx; hh.y = hy;
    __nv_bfloat162 ll = __floats2bfloat162_rn(v.x - __bfloat162float(hx),
                                              v.y - __bfloat162float(hy));
    dst[2u*p]     = *reinterpret_cast<uint32_t*>(&hh);
    dst[2u*p + 1] = *reinterpret_cast<uint32_t*>(&ll);
}

__global__ void convert_v_kernel(const float* __restrict__ V)
{
    __shared__ float st[128][65];
    const int bh = blockIdx.x >> 4;
    const int j0 = (blockIdx.x & 15) * 128;
    const int tid = threadIdx.x;
    const float* vb = V + ((long)bh * Ls + j0) * Dh;
    for (int i = tid; i < 128 * 64; i += 256)
        st[i >> 6][i & 63] = vb[i];
    __syncthreads();
    for (int i = tid; i < 64 * 64; i += 256) {
        int d = i >> 6, jp = i & 63;
        __half2 hh = __floats2half2_rn(st[jp*2][d], st[jp*2 + 1][d]);
        g_VTh[(long)(bh * Dh + d) * 1024 + (j0 >> 1) + jp] =
            *reinterpret_cast<uint32_t*>(&hh);
    }
}

// ---------------- mma helpers ----------------

__device__ __forceinline__ void mma_bf16(float* c, const uint32_t* a, uint32_t b0, uint32_t b1) {
    asm volatile(
        "mma.sync.aligned.m16n8k16.row.col.f32.bf16.bf16.f32 "
        "{%0,%1,%2,%3},{%4,%5,%6,%7},{%8,%9},{%0,%1,%2,%3};\n"
        : "+f"(c[0]), "+f"(c[1]), "+f"(c[2]), "+f"(c[3])
        : "r"(a[0]), "r"(a[1]), "r"(a[2]), "r"(a[3]), "r"(b0), "r"(b1));
}

__device__ __forceinline__ void mma_f16(float* c, const uint32_t* a, uint32_t b0, uint32_t b1) {
    asm volatile(
        "mma.sync.aligned.m16n8k16.row.col.f32.f16.f16.f32 "
        "{%0,%1,%2,%3},{%4,%5,%6,%7},{%8,%9},{%0,%1,%2,%3};\n"
        : "+f"(c[0]), "+f"(c[1]), "+f"(c[2]), "+f"(c[3])
        : "r"(a[0]), "r"(a[1]), "r"(a[2]), "r"(a[3]), "r"(b0), "r"(b1));
}

__device__ __forceinline__ void load_afrag(const uint32_t* __restrict__ g, long rowbase,
                                           int gid, int tig,
                                           uint32_t hi[4][4], uint32_t lo[4][4])
{
    #pragma unroll
    for (int kt = 0; kt < 4; ++kt) {
        long b0 = (rowbase + gid)     * 64 + (kt*8 + tig) * 2;
        long b1 = (rowbase + 8 + gid) * 64 + (kt*8 + tig) * 2;
        uint2 w0 = *(const uint2*)&g[b0];
        uint2 w1 = *(const uint2*)&g[b1];
        uint2 w2 = *(const uint2*)&g[b0 + 8];
        uint2 w3 = *(const uint2*)&g[b1 + 8];
        hi[kt][0] = w0.x; lo[kt][0] = w0.y;
        hi[kt][1] = w1.x; lo[kt][1] = w1.y;
        hi[kt][2] = w2.x; lo[kt][2] = w2.y;
        hi[kt][3] = w3.x; lo[kt][3] = w3.y;
    }
}

// 16-row x 16-col score tile, e = exp(s/8) (sdpa; no shift).
__device__ __forceinline__ void score_exp(const uint32_t* sm, int jg, int gid, int tig,
                                          const uint32_t hi[4][4], const uint32_t lo[4][4],
                                          float e0[4], float e1[4])
{
    float s0[4] = {0,0,0,0}, s1[4] = {0,0,0,0};
    #pragma unroll
    for (int kt = 0; kt < 4; ++kt) {
        const uint32_t* p0 = &sm[(jg + gid)     * KSTR + (kt*8 + tig) * 2];
        const uint32_t* p1 = &sm[(jg + 8 + gid) * KSTR + (kt*8 + tig) * 2];
        uint2 b00 = *(const uint2*)p0;
        uint2 b01 = *(const uint2*)(p0 + 8);
        uint2 b10 = *(const uint2*)p1;
        uint2 b11 = *(const uint2*)(p1 + 8);
        mma_bf16(s0, hi[kt], b00.x, b01.x);
        mma_bf16(s1, hi[kt], b10.x, b11.x);
        mma_bf16(s0, lo[kt], b00.x, b01.x);
        mma_bf16(s1, lo[kt], b10.x, b11.x);
        mma_bf16(s0, hi[kt], b00.y, b01.y);
        mma_bf16(s1, hi[kt], b10.y, b11.y);
    }
    #pragma unroll
    for (int u = 0; u < 4; ++u) {
        e0[u] = __expf(s0[u] * 0.125f);
        e1[u] = __expf(s1[u] * 0.125f);
    }
}

// 32-row x 16-col score tile, e = exp(s/8 - ESH) (attn; shifted for fp16 storage).
__device__ __forceinline__ void score_exp32(const uint32_t* sm, int jg, int gid, int tig,
                                            const uint32_t hi[2][4][4],
                                            const uint32_t lo[2][4][4],
                                            float e[2][2][4])
{
    float s[2][2][4];
    #pragma unroll
    for (int rg = 0; rg < 2; ++rg)
        #pragma unroll
        for (int ng = 0; ng < 2; ++ng)
            #pragma unroll
            for (int u = 0; u < 4; ++u) s[rg][ng][u] = 0.f;

    #pragma unroll
    for (int kt = 0; kt < 4; ++kt) {
        const uint32_t* p0 = &sm[(jg + gid)     * KSTR + (kt*8 + tig) * 2];
        const uint32_t* p1 = &sm[(jg + 8 + gid) * KSTR + (kt*8 + tig) * 2];
        uint2 b00 = *(const uint2*)p0;
        uint2 b01 = *(const uint2*)(p0 + 8);
        uint2 b10 = *(const uint2*)p1;
        uint2 b11 = *(const uint2*)(p1 + 8);
        mma_bf16(s[0][0], hi[0][kt], b00.x, b01.x);
        mma_bf16(s[0][1], hi[0][kt], b10.x, b11.x);
        mma_bf16(s[1][0], hi[1][kt], b00.x, b01.x);
        mma_bf16(s[1][1], hi[1][kt], b10.x, b11.x);
        mma_bf16(s[0][0], lo[0][kt], b00.x, b01.x);
        mma_bf16(s[0][1], lo[0][kt], b10.x, b11.x);
        mma_bf16(s[1][0], lo[1][kt], b00.x, b01.x);
        mma_bf16(s[1][1], lo[1][kt], b10.x, b11.x);
        mma_bf16(s[0][0], hi[0][kt], b00.y, b01.y);
        mma_bf16(s[0][1], hi[0][kt], b10.y, b11.y);
        mma_bf16(s[1][0], hi[1][kt], b00.y, b01.y);
        mma_bf16(s[1][1], hi[1][kt], b10.y, b11.y);
    }
    #pragma unroll
    for (int rg = 0; rg < 2; ++rg)
        #pragma unroll
        for (int ng = 0; ng < 2; ++ng)
            #pragma unroll
            for (int u = 0; u < 4; ++u)
                e[rg][ng][u] = __expf(fmaf(s[rg][ng][u], 0.125f, -ESH));
}

// ---------------- cp.async helpers ----------------

__device__ __forceinline__ void cpasync16(uint32_t smaddr, const void* gptr) {
    asm volatile("cp.async.cg.shared.global [%0], [%1], 16;\n"
                 :: "r"(smaddr), "l"(gptr));
}
#define CP_COMMIT()  asm volatile("cp.async.commit_group;\n" ::: "memory")
#define CP_WAIT(N)   asm volatile("cp.async.wait_group %0;\n" :: "n"(N) : "memory")

// ---------------- attn pass: one matrix per block, 64 rows (round-14, unchanged) ----------------

__global__ void __launch_bounds__(NTHREADS, 1)
attn_exp_kernel()
{
    extern __shared__ uint32_t smw[];
    uint32_t* buf[2] = { smw, smw + ATTN_TILEW };
    float* red = (float*)(smw + 2*ATTN_TILEW);   // [8 cg][64 rows]

    const int tid  = threadIdx.x;
    const int lane = tid & 31, warp = tid >> 5;
    const int gid  = lane >> 2, tig = lane & 3;
    const int rw   = warp >> 3;
    const int cg   = warp & 7;
    const int jg   = cg * 16;
    const int mat  = blockIdx.x & 1;
    const int strip= (blockIdx.x >> 1) & 31;
    const int bh   = blockIdx.x >> 6;
    const int l0   = strip * 64;
    const long rb  = (long)bh * Ls;

    const uint32_t* gA = mat ? g_K : g_Q;

    uint32_t ahi[2][4][4], alo[2][4][4];
    load_afrag(gA, rb + l0 + rw*32,      gid, tig, ahi[0], alo[0]);
    load_afrag(gA, rb + l0 + rw*32 + 16, gid, tig, ahi[1], alo[1]);

    const float4* gA4 = (const float4*)(gA + rb * 64);
    uint32_t smb[2];
    smb[0] = (uint32_t)__cvta_generic_to_shared(buf[0]);
    smb[1] = (uint32_t)__cvta_generic_to_shared(buf[1]);

    #define ISSUE_TILE(ct, s) do { \
        const float4* ap = gA4 + (ct) * 2048; \
        _Pragma("unroll") \
        for (int u = 0; u < 4; ++u) { \
            int i = tid + u*512; int j = i >> 4, qq = i & 15; \
            cpasync16(smb[s] + (uint32_t)(j * (KSTR/4) + qq) * 16u, ap + i); \
        } \
        CP_COMMIT(); \
    } while (0)

    __half* ob = (mat ? g_EKh : g_EQh) + (rb + l0 + rw*32) * (long)Ls;

    float ssum[2][2] = {{0.f,0.f},{0.f,0.f}};

    ISSUE_TILE(0, 0);
    #pragma unroll 1
    for (int ct = 0; ct < NTILES; ++ct) {
        const int s = ct & 1;
        if (ct + 1 < NTILES) { ISSUE_TILE(ct + 1, s ^ 1); CP_WAIT(1); }
        else                 { CP_WAIT(0); }
        __syncthreads();

        float e[2][2][4];
        score_exp32(buf[s], jg, gid, tig, ahi, alo, e);

        int c0 = ct * NT + jg + tig * 2;
        #pragma unroll
        for (int rg = 0; rg < 2; ++rg) {
            ssum[rg][0] += e[rg][0][0] + e[rg][0][1] + e[rg][1][0] + e[rg][1][1];
            ssum[rg][1] += e[rg][0][2] + e[rg][0][3] + e[rg][1][2] + e[rg][1][3];
            __half* r0 = ob + (long)(rg*16 + gid)     * Ls + c0;
            __half* r1 = ob + (long)(rg*16 + gid + 8) * Ls + c0;
            *(__half2*)r0       = __floats2half2_rn(e[rg][0][0], e[rg][0][1]);
            *(__half2*)(r0 + 8) = __floats2half2_rn(e[rg][1][0], e[rg][1][1]);
            *(__half2*)r1       = __floats2half2_rn(e[rg][0][2], e[rg][0][3]);
            *(__half2*)(r1 + 8) = __floats2half2_rn(e[rg][1][2], e[rg][1][3]);
        }
        __syncthreads();
    }
    #undef ISSUE_TILE

    #pragma unroll
    for (int rg = 0; rg < 2; ++rg)
        #pragma unroll
        for (int h = 0; h < 2; ++h) {
            ssum[rg][h] += __shfl_xor_sync(~0u, ssum[rg][h], 1);
            ssum[rg][h] += __shfl_xor_sync(~0u, ssum[rg][h], 2);
        }
    if (tig == 0) {
        red[cg*64 + rw*32 + gid]      = ssum[0][0];
        red[cg*64 + rw*32 + 8 + gid]  = ssum[0][1];
        red[cg*64 + rw*32 + 16 + gid] = ssum[1][0];
        red[cg*64 + rw*32 + 24 + gid] = ssum[1][1];
    }
    __syncthreads();
    if (tid < 64) {
        float t = 0.f;
        #pragma unroll
        for (int c = 0; c < 8; ++c) t += red[c*64 + tid];
        (mat ? g_rsK : g_rsQ)[bh * Ls + l0 + tid] = t;
    }
}

// ---------------- normalize + add: out = EQ/sq + EK/sk (round-14, unchanged) ----------------

__global__ void __launch_bounds__(128)
normalize_add_kernel(float* __restrict__ outAttn)
{
    const int row = blockIdx.x;
    const float invq = 1.0f / g_rsQ[row];
    const float invk = 1.0f / g_rsK[row];
    const uint4* eq = (const uint4*)(g_EQh + (long)row * Ls);
    const uint4* ek = (const uint4*)(g_EKh + (long)row * Ls);
    float4* oa = (float4*)(outAttn + (long)row * Ls);
    #pragma unroll
    for (int u = 0; u < 2; ++u) {
        int i = threadIdx.x + u * 128;
        uint4 a = eq[i], b = ek[i];
        const __half2* ah  = (const __half2*)&a;
        const __half2* bh2 = (const __half2*)&b;
        float2 f0 = __half22float2(ah[0]), f1 = __half22float2(ah[1]);
        float2 f2 = __half22float2(ah[2]), f3 = __half22float2(ah[3]);
        float2 g0 = __half22float2(bh2[0]), g1 = __half22float2(bh2[1]);
        float2 g2 = __half22float2(bh2[2]), g3 = __half22float2(bh2[3]);
        float4 o0, o1;
        o0.x = f0.x*invq + g0.x*invk;  o0.y = f0.y*invq + g0.y*invk;
        o0.z = f1.x*invq + g1.x*invk;  o0.w = f1.y*invq + g1.y*invk;
        o1.x = f2.x*invq + g2.x*invk;  o1.y = f2.y*invq + g2.y*invk;
        o1.z = f3.x*invq + g3.x*invk;  o1.w = f3.y*invq + g3.y*invk;
        oa[i*2]     = o0;
        oa[i*2 + 1] = o1;
    }
}

// ---------------- sdpa: 64 rows x half the columns per block (split-j) ----------------
// Grid 1024 = 512 strips x 2 j-halves. Each block: 16 tiles of NT=64 cols over its
// half; staged K/V bytes per Q-row are HALF the previous scheme. Writes
// unnormalized partial O + partial row sums; combine_o_kernel finishes.
// Warps: rg = warp>>2 (rows rg*16..+16), cw = warp&3 (cols cw*16..+16 of tile).

__global__ void __launch_bounds__(NTHREADS, 1)
sdpa_flash_kernel()
{
    extern __shared__ uint32_t smw[];
    uint32_t* bufK   = smw;                       // 64 rows x KSTR
    uint32_t* bufV   = smw + 64 * KSTR;           // 64 d-rows x VSTR3
    float*    redsum = (float*)(smw + SDPA_REDO_W);   // [4 rg][4 cw][16 rows]
    float*    redO   = (float*)smw;               // 16 warps x 1024, aliases tiles

    const int tid  = threadIdx.x;
    const int lane = tid & 31, warp = tid >> 5;
    const int gid  = lane >> 2, tig = lane & 3;
    const int rg   = warp >> 2;
    const int cw   = warp & 3;
    const int jg   = cw * 16;
    const int jp0  = cw * 8;
    const int half = blockIdx.x & 1;
    const int strip= blockIdx.x >> 1;
    const int bh   = strip >> 5;
    const int l0   = (strip & 31) * 64;
    const long rb  = (long)bh * Ls;

    uint32_t qhi[4][4], qlo[4][4];
    load_afrag(g_Q, rb + l0 + rg * 16, gid, tig, qhi, qlo);

    float oacc[8][4];
    #pragma unroll
    for (int dg = 0; dg < 8; ++dg)
        #pragma unroll
        for (int u = 0; u < 4; ++u) oacc[dg][u] = 0.f;
    float s0sum = 0.f, s1sum = 0.f;

    float4* smK4 = (float4*)bufK;
    float4* smV4 = (float4*)bufV;
    const float4* gK4 = (const float4*)(g_K + rb * 64) + (long)half * 16384;
    const float4* gV4 = (const float4*)(g_VTh + (long)bh * Dh * 1024) + half * 128;

    float4 pk[2], pv;
    #define PREF_KV(ct) do { \
        const float4* ak = gK4 + (ct) * 1024; \
        pk[0] = ak[tid]; pk[1] = ak[tid + 512]; \
        pv = gV4[(long)(tid >> 3) * 256 + (ct) * 8 + (tid & 7)]; \
    } while (0)
    #define STORE_KV() do { \
        _Pragma("unroll") \
        for (int u = 0; u < 2; ++u) { int i = tid + u*512; \
            smK4[(i >> 4) * (KSTR/4) + (i & 15)] = pk[u]; } \
        smV4[(tid >> 3) * (VSTR3/4) + (tid & 7)] = pv; \
    } while (0)

    PREF_KV(0);
    #pragma unroll 1
    for (int ct = 0; ct < 16; ++ct) {
        __syncthreads();
        STORE_KV();
        __syncthreads();
        if (ct + 1 < 16) PREF_KV(ct + 1);

        float e0[4], e1[4];
        score_exp(bufK, jg, gid, tig, qhi, qlo, e0, e1);
        s0sum += e0[0] + e0[1] + e1[0] + e1[1];
        s1sum += e0[2] + e0[3] + e1[2] + e1[3];

        uint32_t pa[4];
        { __half2 h;
          h = __floats2half2_rn(e0[0], e0[1]); pa[0] = *(uint32_t*)&h;
          h = __floats2half2_rn(e0[2], e0[3]); pa[1] = *(uint32_t*)&h;
          h = __floats2half2_rn(e1[0], e1[1]); pa[2] = *(uint32_t*)&h;
          h = __floats2half2_rn(e1[2], e1[3]); pa[3] = *(uint32_t*)&h; }

        #pragma unroll
        for (int dg = 0; dg < 8; ++dg) {
            uint32_t b0 = bufV[(dg*8 + gid) * VSTR3 + jp0 + tig];
            uint32_t b1 = bufV[(dg*8 + gid) * VSTR3 + jp0 + tig + 4];
            mma_f16(oacc[dg], pa, b0, b1);
        }
    }
    #undef PREF_KV
    #undef STORE_KV

    s0sum += __shfl_xor_sync(~0u, s0sum, 1); s0sum += __shfl_xor_sync(~0u, s0sum, 2);
    s1sum += __shfl_xor_sync(~0u, s1sum, 1); s1sum += __shfl_xor_sync(~0u, s1sum, 2);
    __syncthreads();                       // all tile-buffer reads complete
    if (tig == 0) {
        redsum[warp*16 + gid]     = s0sum;
        redsum[warp*16 + 8 + gid] = s1sum;
    }
    __syncthreads();
    // partial O to smem (clobbers tile buffers — safe after sync)
    #pragma unroll
    for (int dg = 0; dg < 8; ++dg) {
        float* r = redO + warp * 1024;
        int d = dg*8 + tig*2;
        r[gid*64 + d]           = oacc[dg][0];
        r[gid*64 + d + 1]       = oacc[dg][1];
        r[(gid+8)*64 + d]       = oacc[dg][2];
        r[(gid+8)*64 + d + 1]   = oacc[dg][3];
    }
    __syncthreads();

    // partial row sums (64 rows) and partial O (64x64) to global
    if (tid < 64) {
        int rgi = tid >> 4, lr = tid & 15;
        float t = 0.f;
        #pragma unroll
        for (int c = 0; c < 4; ++c) t += redsum[(rgi*4 + c)*16 + lr];
        g_ssum[half * (BH*Ls) + bh * Ls + l0 + tid] = t;
    }
    float* op = g_Opart + (long)half * (BH*Ls*Dh) + ((long)(bh * Ls + l0)) * Dh;
    for (int i = tid; i < 64 * Dh; i += NTHREADS) {
        int r = i >> 6;
        int rgi = r >> 4, lr = r & 15, d = i & 63;
        float v = 0.f;
        #pragma unroll
        for (int c = 0; c < 4; ++c) v += redO[(rgi*4 + c)*1024 + lr*64 + d];
        op[i] = v;
    }
}

// ---------------- combine: O = (P0 + P1) / (s0 + s1) ----------------

__global__ void __launch_bounds__(256)
combine_o_kernel(float* __restrict__ outO)
{
    int i = blockIdx.x * 1024 + threadIdx.x;
    #pragma unroll
    for (int u = 0; u < 4; ++u, i += 256) {
        int row = i >> 6;
        float s = g_ssum[row] + g_ssum[BH*Ls + row];
        outO[i] = (g_Opart[i] + g_Opart[(long)BH*Ls*Dh + i]) * (1.0f / s);
    }
}

// ---------------- launch ----------------

extern "C" void kernel_launch(void* const* d_in, const int* in_sizes, int n_in,
                              void* d_out, int out_size)
{
    const float* q = (const float*)d_in[0];
    const float* k = (const float*)d_in[1];
    const float* v = (const float*)d_in[2];

    float* outO    = (float*)d_out;             // [2,8,2048,64]
    float* outAttn = (float*)d_out + 2097152;   // [2,8,2048,2048]

    cudaFuncSetAttribute(attn_exp_kernel,
                         cudaFuncAttributeMaxDynamicSharedMemorySize, ATTN_SMEM_BYTES);
    cudaFuncSetAttribute(sdpa_flash_kernel,
                         cudaFuncAttributeMaxDynamicSharedMemorySize, SDPA_SMEM_BYTES);

    convert_qk_kernel<<<(2 * BH * Ls * 32) / 256, 256>>>(q, k);
    convert_v_kernel<<<BH * 16, 256>>>(v);
    attn_exp_kernel<<<1024, NTHREADS, ATTN_SMEM_BYTES>>>();
    normalize_add_kernel<<<BH * Ls, 128>>>(outAttn);
    sdpa_flash_kernel<<<1024, NTHREADS, SDPA_SMEM_BYTES>>>();
    combine_o_kernel<<<2048, 256>>>(outO);
}

// round 17
// speedup vs baseline: 1.6567x; 1.2328x over previous
#include <cuda_runtime.h>
#include <cuda_bf16.h>
#include <cuda_fp16.h>
#include <cstdint>

// B=2,H=8 -> BH=16 heads; L=S=2048; D=64; fp32 in/out.
#define BH        16
#define Ls        2048
#define Dh        64
#define NT        128
#define NTILES    16
#define NTHREADS  512
#define RSTR      36        // smem words per staged fp16 row (32 data + 4 pad)

// sdpa (split-j): tiles 64*36 + 64*36 = 4608 words; epilogue redO needs 16384.
#define SDPA_REDO_W     16384
#define SDPA_SMEM_BYTES ((SDPA_REDO_W + 256 + 16) * 4)    // 66624

#define ATTN_TILEW       (128*RSTR)                        // 4608 words
#define ATTN_SMEM_BYTES  ((2*ATTN_TILEW + 512 + 16) * 4)   // 38976

// Exponent shift: stored values are exp(s/8 - ESH); cancels in normalization.
#define ESH 8.0f

// fp16-packed Q/K rows (32 words/row) and V^T.
__device__ uint32_t g_Qh [BH * Ls * 32];
__device__ uint32_t g_Kh [BH * Ls * 32];
__device__ uint32_t g_VTh[BH * Dh * 1024];
// Unnormalized shifted exp scratch (fp16) + row sums.
__device__ __half g_EQh[(long)BH * Ls * Ls];
__device__ __half g_EKh[(long)BH * Ls * Ls];
__device__ float g_rsQ[BH * Ls];
__device__ float g_rsK[BH * Ls];
// sdpa split-j partials: [half][row][d] and [half][row].
__device__ float g_Opart[2 * BH * Ls * Dh];
__device__ float g_ssum [2 * BH * Ls];

// ---------------- converts ----------------

__global__ void convert_qk_kernel(const float* __restrict__ Q, const float* __restrict__ K)
{
    const unsigned NPAIR = BH * Ls * 32;
    unsigned i = blockIdx.x * 256 + threadIdx.x;
    const float2* src = (i < NPAIR) ? (const float2*)Q : (const float2*)K;
    uint32_t*     dst = (i < NPAIR) ? g_Qh : g_Kh;
    unsigned p = (i < NPAIR) ? i : i - NPAIR;
    float2 v = src[p];
    __half2 h = __floats2half2_rn(v.x, v.y);
    dst[p] = *reinterpret_cast<uint32_t*>(&h);
}

__global__ void convert_v_kernel(const float* __restrict__ V)
{
    __shared__ float st[128][65];
    const int bh = blockIdx.x >> 4;
    const int j0 = (blockIdx.x & 15) * 128;
    const int tid = threadIdx.x;
    const float* vb = V + ((long)bh * Ls + j0) * Dh;
    for (int i = tid; i < 128 * 64; i += 256)
        st[i >> 6][i & 63] = vb[i];
    __syncthreads();
    for (int i = tid; i < 64 * 64; i += 256) {
        int d = i >> 6, jp = i & 63;
        __half2 hh = __floats2half2_rn(st[jp*2][d], st[jp*2 + 1][d]);
        g_VTh[(long)(bh * Dh + d) * 1024 + (j0 >> 1) + jp] =
            *reinterpret_cast<uint32_t*>(&hh);
    }
}

// ---------------- mma helpers ----------------

__device__ __forceinline__ void mma_f16(float* c, const uint32_t* a, uint32_t b0, uint32_t b1) {
    asm volatile(
        "mma.sync.aligned.m16n8k16.row.col.f32.f16.f16.f32 "
        "{%0,%1,%2,%3},{%4,%5,%6,%7},{%8,%9},{%0,%1,%2,%3};\n"
        : "+f"(c[0]), "+f"(c[1]), "+f"(c[2]), "+f"(c[3])
        : "r"(a[0]), "r"(a[1]), "r"(a[2]), "r"(a[3]), "r"(b0), "r"(b1));
}

// fp16 A fragments for 16 rows x k=64 (16 regs).
__device__ __forceinline__ void load_afrag_h(const uint32_t* __restrict__ g, long rowbase,
                                             int gid, int tig, uint32_t a[4][4])
{
    #pragma unroll
    for (int kt = 0; kt < 4; ++kt) {
        long b0 = (rowbase + gid)     * 32 + kt*8 + tig;
        long b1 = (rowbase + 8 + gid) * 32 + kt*8 + tig;
        a[kt][0] = g[b0];
        a[kt][1] = g[b1];
        a[kt][2] = g[b0 + 4];
        a[kt][3] = g[b1 + 4];
    }
}

// 16-row x 16-col score tile, e = exp(s/8) (sdpa). 8 MMAs.
__device__ __forceinline__ void score_exp_h(const uint32_t* sm, int jg, int gid, int tig,
                                            const uint32_t a[4][4],
                                            float e0[4], float e1[4])
{
    float s0[4] = {0,0,0,0}, s1[4] = {0,0,0,0};
    #pragma unroll
    for (int kt = 0; kt < 4; ++kt) {
        int w0 = kt*8 + tig;
        uint32_t b00 = sm[(jg + gid)     * RSTR + w0];
        uint32_t b01 = sm[(jg + gid)     * RSTR + w0 + 4];
        uint32_t b10 = sm[(jg + 8 + gid) * RSTR + w0];
        uint32_t b11 = sm[(jg + 8 + gid) * RSTR + w0 + 4];
        mma_f16(s0, a[kt], b00, b01);
        mma_f16(s1, a[kt], b10, b11);
    }
    #pragma unroll
    for (int u = 0; u < 4; ++u) {
        e0[u] = __expf(s0[u] * 0.125f);
        e1[u] = __expf(s1[u] * 0.125f);
    }
}

// 32-row x 16-col score tile, e = exp(s/8 - ESH) (attn). 16 MMAs.
__device__ __forceinline__ void score_exp32_h(const uint32_t* sm, int jg, int gid, int tig,
                                              const uint32_t a[2][4][4],
                                              float e[2][2][4])
{
    float s[2][2][4];
    #pragma unroll
    for (int rg = 0; rg < 2; ++rg)
        #pragma unroll
        for (int ng = 0; ng < 2; ++ng)
            #pragma unroll
            for (int u = 0; u < 4; ++u) s[rg][ng][u] = 0.f;

    #pragma unroll
    for (int kt = 0; kt < 4; ++kt) {
        int w0 = kt*8 + tig;
        uint32_t b00 = sm[(jg + gid)     * RSTR + w0];
        uint32_t b01 = sm[(jg + gid)     * RSTR + w0 + 4];
        uint32_t b10 = sm[(jg + 8 + gid) * RSTR + w0];
        uint32_t b11 = sm[(jg + 8 + gid) * RSTR + w0 + 4];
        mma_f16(s[0][0], a[0][kt], b00, b01);
        mma_f16(s[0][1], a[0][kt], b10, b11);
        mma_f16(s[1][0], a[1][kt], b00, b01);
        mma_f16(s[1][1], a[1][kt], b10, b11);
    }
    #pragma unroll
    for (int rg = 0; rg < 2; ++rg)
        #pragma unroll
        for (int ng = 0; ng < 2; ++ng)
            #pragma unroll
            for (int u = 0; u < 4; ++u)
                e[rg][ng][u] = __expf(fmaf(s[rg][ng][u], 0.125f, -ESH));
}

// ---------------- cp.async helpers ----------------

__device__ __forceinline__ void cpasync16(uint32_t smaddr, const void* gptr) {
    asm volatile("cp.async.cg.shared.global [%0], [%1], 16;\n"
                 :: "r"(smaddr), "l"(gptr));
}
#define CP_COMMIT()  asm volatile("cp.async.commit_group;\n" ::: "memory")
#define CP_WAIT(N)   asm volatile("cp.async.wait_group %0;\n" :: "n"(N) : "memory")

// ---------------- attn pass: one matrix per block, 64 rows, fp16 scores ----------------

__global__ void __launch_bounds__(NTHREADS, 1)
attn_exp_kernel()
{
    extern __shared__ uint32_t smw[];
    uint32_t* buf[2] = { smw, smw + ATTN_TILEW };
    float* red = (float*)(smw + 2*ATTN_TILEW);   // [8 cg][64 rows]

    const int tid  = threadIdx.x;
    const int lane = tid & 31, warp = tid >> 5;
    const int gid  = lane >> 2, tig = lane & 3;
    const int rw   = warp >> 3;          // rowgroup 0/1 -> rows rw*32..+32
    const int cg   = warp & 7;
    const int jg   = cg * 16;
    const int mat  = blockIdx.x & 1;
    const int strip= (blockIdx.x >> 1) & 31;
    const int bh   = blockIdx.x >> 6;
    const int l0   = strip * 64;
    const long rb  = (long)bh * Ls;

    const uint32_t* gA = mat ? g_Kh : g_Qh;

    uint32_t ah[2][4][4];
    load_afrag_h(gA, rb + l0 + rw*32,      gid, tig, ah[0]);
    load_afrag_h(gA, rb + l0 + rw*32 + 16, gid, tig, ah[1]);

    const float4* gA4 = (const float4*)(gA + rb * 32);
    uint32_t smb[2];
    smb[0] = (uint32_t)__cvta_generic_to_shared(buf[0]);
    smb[1] = (uint32_t)__cvta_generic_to_shared(buf[1]);

    // 128 rows x 32 words = 1024 float4 per tile.
    #define ISSUE_TILE(ct, s) do { \
        const float4* ap = gA4 + (ct) * 1024; \
        _Pragma("unroll") \
        for (int u = 0; u < 2; ++u) { \
            int i = tid + u*512; int j = i >> 3, qq = i & 7; \
            cpasync16(smb[s] + (uint32_t)(j * 9 + qq) * 16u, ap + i); \
        } \
        CP_COMMIT(); \
    } while (0)

    __half* ob = (mat ? g_EKh : g_EQh) + (rb + l0 + rw*32) * (long)Ls;

    float ssum[2][2] = {{0.f,0.f},{0.f,0.f}};

    ISSUE_TILE(0, 0);
    #pragma unroll 1
    for (int ct = 0; ct < NTILES; ++ct) {
        const int s = ct & 1;
        if (ct + 1 < NTILES) { ISSUE_TILE(ct + 1, s ^ 1); CP_WAIT(1); }
        else                 { CP_WAIT(0); }
        __syncthreads();

        float e[2][2][4];
        score_exp32_h(buf[s], jg, gid, tig, ah, e);

        int c0 = ct * NT + jg + tig * 2;
        #pragma unroll
        for (int rg = 0; rg < 2; ++rg) {
            ssum[rg][0] += e[rg][0][0] + e[rg][0][1] + e[rg][1][0] + e[rg][1][1];
            ssum[rg][1] += e[rg][0][2] + e[rg][0][3] + e[rg][1][2] + e[rg][1][3];
            __half* r0 = ob + (long)(rg*16 + gid)     * Ls + c0;
            __half* r1 = ob + (long)(rg*16 + gid + 8) * Ls + c0;
            *(__half2*)r0       = __floats2half2_rn(e[rg][0][0], e[rg][0][1]);
            *(__half2*)(r0 + 8) = __floats2half2_rn(e[rg][1][0], e[rg][1][1]);
            *(__half2*)r1       = __floats2half2_rn(e[rg][0][2], e[rg][0][3]);
            *(__half2*)(r1 + 8) = __floats2half2_rn(e[rg][1][2], e[rg][1][3]);
        }
        __syncthreads();
    }
    #undef ISSUE_TILE

    #pragma unroll
    for (int rg = 0; rg < 2; ++rg)
        #pragma unroll
        for (int h = 0; h < 2; ++h) {
            ssum[rg][h] += __shfl_xor_sync(~0u, ssum[rg][h], 1);
            ssum[rg][h] += __shfl_xor_sync(~0u, ssum[rg][h], 2);
        }
    if (tig == 0) {
        red[cg*64 + rw*32 + gid]      = ssum[0][0];
        red[cg*64 + rw*32 + 8 + gid]  = ssum[0][1];
        red[cg*64 + rw*32 + 16 + gid] = ssum[1][0];
        red[cg*64 + rw*32 + 24 + gid] = ssum[1][1];
    }
    __syncthreads();
    if (tid < 64) {
        float t = 0.f;
        #pragma unroll
        for (int c = 0; c < 8; ++c) t += red[c*64 + tid];
        (mat ? g_rsK : g_rsQ)[bh * Ls + l0 + tid] = t;
    }
}

// ---------------- normalize + add: out = EQ/sq + EK/sk ----------------

__global__ void __launch_bounds__(128)
normalize_add_kernel(float* __restrict__ outAttn)
{
    const int row = blockIdx.x;
    const float invq = 1.0f / g_rsQ[row];
    const float invk = 1.0f / g_rsK[row];
    const uint4* eq = (const uint4*)(g_EQh + (long)row * Ls);
    const uint4* ek = (const uint4*)(g_EKh + (long)row * Ls);
    float4* oa = (float4*)(outAttn + (long)row * Ls);
    #pragma unroll
    for (int u = 0; u < 2; ++u) {
        int i = threadIdx.x + u * 128;
        uint4 a = eq[i], b = ek[i];
        const __half2* ah  = (const __half2*)&a;
        const __half2* bh2 = (const __half2*)&b;
        float2 f0 = __half22float2(ah[0]), f1 = __half22float2(ah[1]);
        float2 f2 = __half22float2(ah[2]), f3 = __half22float2(ah[3]);
        float2 g0 = __half22float2(bh2[0]), g1 = __half22float2(bh2[1]);
        float2 g2 = __half22float2(bh2[2]), g3 = __half22float2(bh2[3]);
        float4 o0, o1;
        o0.x = f0.x*invq + g0.x*invk;  o0.y = f0.y*invq + g0.y*invk;
        o0.z = f1.x*invq + g1.x*invk;  o0.w = f1.y*invq + g1.y*invk;
        o1.x = f2.x*invq + g2.x*invk;  o1.y = f2.y*invq + g2.y*invk;
        o1.z = f3.x*invq + g3.x*invk;  o1.w = f3.y*invq + g3.y*invk;
        oa[i*2]     = o0;
        oa[i*2 + 1] = o1;
    }
}

// ---------------- sdpa: split-j, fp16 scores ----------------
// Grid 1024 = 512 strips x 2 j-halves; block = 64 rows x 1024 cols.
// Warps: rg = warp>>2 (rows rg*16..+16), cw = warp&3 (cols cw*16 of tile).

__global__ void __launch_bounds__(NTHREADS, 1)
sdpa_flash_kernel()
{
    extern __shared__ uint32_t smw[];
    uint32_t* bufK   = smw;                       // 64 rows x RSTR
    uint32_t* bufV   = smw + 64 * RSTR;           // 64 d-rows x RSTR
    float*    redsum = (float*)(smw + SDPA_REDO_W);
    float*    redO   = (float*)smw;               // 16 warps x 1024, aliases tiles

    const int tid  = threadIdx.x;
    const int lane = tid & 31, warp = tid >> 5;
    const int gid  = lane >> 2, tig = lane & 3;
    const int rg   = warp >> 2;
    const int cw   = warp & 3;
    const int jg   = cw * 16;
    const int jp0  = cw * 8;
    const int half = blockIdx.x & 1;
    const int strip= blockIdx.x >> 1;
    const int bh   = strip >> 5;
    const int l0   = (strip & 31) * 64;
    const long rb  = (long)bh * Ls;

    uint32_t qh[4][4];
    load_afrag_h(g_Qh, rb + l0 + rg * 16, gid, tig, qh);

    float oacc[8][4];
    #pragma unroll
    for (int dg = 0; dg < 8; ++dg)
        #pragma unroll
        for (int u = 0; u < 4; ++u) oacc[dg][u] = 0.f;
    float s0sum = 0.f, s1sum = 0.f;

    float4* smK4 = (float4*)bufK;
    float4* smV4 = (float4*)bufV;
    const float4* gK4 = (const float4*)(g_Kh + (rb + half * 1024) * 32);
    const float4* gV4 = (const float4*)(g_VTh + (long)bh * Dh * 1024) + half * 128;

    float4 pk, pv;
    #define PREF_KV(ct) do { \
        pk = gK4[(ct) * 512 + tid]; \
        pv = gV4[(long)(tid >> 3) * 256 + (ct) * 8 + (tid & 7)]; \
    } while (0)
    #define STORE_KV() do { \
        smK4[(tid >> 3) * 9 + (tid & 7)] = pk; \
        smV4[(tid >> 3) * 9 + (tid & 7)] = pv; \
    } while (0)

    PREF_KV(0);
    #pragma unroll 1
    for (int ct = 0; ct < 16; ++ct) {
        __syncthreads();
        STORE_KV();
        __syncthreads();
        if (ct + 1 < 16) PREF_KV(ct + 1);

        float e0[4], e1[4];
        score_exp_h(bufK, jg, gid, tig, qh, e0, e1);
        s0sum += e0[0] + e0[1] + e1[0] + e1[1];
        s1sum += e0[2] + e0[3] + e1[2] + e1[3];

        uint32_t pa[4];
        { __half2 h;
          h = __floats2half2_rn(e0[0], e0[1]); pa[0] = *(uint32_t*)&h;
          h = __floats2half2_rn(e0[2], e0[3]); pa[1] = *(uint32_t*)&h;
          h = __floats2half2_rn(e1[0], e1[1]); pa[2] = *(uint32_t*)&h;
          h = __floats2half2_rn(e1[2], e1[3]); pa[3] = *(uint32_t*)&h; }

        #pragma unroll
        for (int dg = 0; dg < 8; ++dg) {
            uint32_t b0 = bufV[(dg*8 + gid) * RSTR + jp0 + tig];
            uint32_t b1 = bufV[(dg*8 + gid) * RSTR + jp0 + tig + 4];
            mma_f16(oacc[dg], pa, b0, b1);
        }
    }
    #undef PREF_KV
    #undef STORE_KV

    s0sum += __shfl_xor_sync(~0u, s0sum, 1); s0sum += __shfl_xor_sync(~0u, s0sum, 2);
    s1sum += __shfl_xor_sync(~0u, s1sum, 1); s1sum += __shfl_xor_sync(~0u, s1sum, 2);
    __syncthreads();
    if (tig == 0) {
        redsum[warp*16 + gid]     = s0sum;
        redsum[warp*16 + 8 + gid] = s1sum;
    }
    __syncthreads();
    #pragma unroll
    for (int dg = 0; dg < 8; ++dg) {
        float* r = redO + warp * 1024;
        int d = dg*8 + tig*2;
        r[gid*64 + d]           = oacc[dg][0];
        r[gid*64 + d + 1]       = oacc[dg][1];
        r[(gid+8)*64 + d]       = oacc[dg][2];
        r[(gid+8)*64 + d + 1]   = oacc[dg][3];
    }
    __syncthreads();

    if (tid < 64) {
        int rgi = tid >> 4, lr = tid & 15;
        float t = 0.f;
        #pragma unroll
        for (int c = 0; c < 4; ++c) t += redsum[(rgi*4 + c)*16 + lr];
        g_ssum[half * (BH*Ls) + bh * Ls + l0 + tid] = t;
    }
    float* op = g_Opart + (long)half * (BH*Ls*Dh) + ((long)(bh * Ls + l0)) * Dh;
    for (int i = tid; i < 64 * Dh; i += NTHREADS) {
        int r = i >> 6;
        int rgi = r >> 4, lr = r & 15, d = i & 63;
        float v = 0.f;
        #pragma unroll
        for (int c = 0; c < 4; ++c) v += redO[(rgi*4 + c)*1024 + lr*64 + d];
        op[i] = v;
    }
}

// ---------------- combine: O = (P0 + P1) / (s0 + s1) ----------------

__global__ void __launch_bounds__(256)
combine_o_kernel(float* __restrict__ outO)
{
    int i = blockIdx.x * 1024 + threadIdx.x;
    #pragma unroll
    for (int u = 0; u < 4; ++u, i += 256) {
        int row = i >> 6;
        float s = g_ssum[row] + g_ssum[BH*Ls + row];
        outO[i] = (g_Opart[i] + g_Opart[(long)BH*Ls*Dh + i]) * (1.0f / s);
    }
}

// ---------------- launch ----------------

extern "C" void kernel_launch(void* const* d_in, const int* in_sizes, int n_in,
                              void* d_out, int out_size)
{
    const float* q = (const float*)d_in[0];
    const float* k = (const float*)d_in[1];
    const float* v = (const float*)d_in[2];

    float* outO    = (float*)d_out;             // [2,8,2048,64]
    float* outAttn = (float*)d_out + 2097152;   // [2,8,2048,2048]

    cudaFuncSetAttribute(attn_exp_kernel,
                         cudaFuncAttributeMaxDynamicSharedMemorySize, ATTN_SMEM_BYTES);
    cudaFuncSetAttribute(sdpa_flash_kernel,
                         cudaFuncAttributeMaxDynamicSharedMemorySize, SDPA_SMEM_BYTES);

    convert_qk_kernel<<<(2 * BH * Ls * 32) / 256, 256>>>(q, k);
    convert_v_kernel<<<BH * 16, 256>>>(v);
    attn_exp_kernel<<<1024, NTHREADS, ATTN_SMEM_BYTES>>>();
    normalize_add_kernel<<<BH * Ls, 128>>>(outAttn);
    sdpa_flash_kernel<<<1024, NTHREADS, SDPA_SMEM_BYTES>>>();
    combine_o_kernel<<<2048, 256>>>(outO);
}